// round 11
// baseline (speedup 1.0000x reference)
#include <cuda_runtime.h>
#include <cstdint>

#define THREADS 256
#define M_TILE  128

// ---------------- SMEM layout (bytes) ----------------
// X digit planes: [128 rows][64 B] (one 64-k segment; 64B rows, SW64)
// W planes:       [64 n-rows][256 B] (k-bytes padded to 256; SW256)
#define OFF_B1   0
#define OFF_B2   256
#define OFF_XD1  1024
#define OFF_XD0  (OFF_XD1 + 8192)      //  9216
#define OFF_W1E1 (OFF_XD0 + 8192)      // 17408
#define OFF_W1E0 (OFF_W1E1 + 16384)    // 33792
#define OFF_W2E1 (OFF_W1E0 + 16384)    // 50176
#define OFF_W2E0 (OFF_W2E1 + 16384)    // 66560
#define SMEM_BYTES (OFF_W2E0 + 16384)  // 82944 -> 2 CTAs/SM

// ---------------- helpers ----------------
__device__ __forceinline__ uint32_t smem_u32(const void* p) {
    uint32_t a;
    asm("{ .reg .u64 t; cvta.to.shared.u64 t, %1; cvt.u32.u64 %0, t; }" : "=r"(a) : "l"(p));
    return a;
}
// 64B-row swizzle: XOR 16B-chunk bits [4:5] with row bits [7:8]
__device__ __forceinline__ uint32_t sw64(uint32_t o)  { return o ^ ((o >> 3) & 0x30); }
// 256B-row swizzle: XOR 16B-chunk bits [4:6] with row bits [8:10]
__device__ __forceinline__ uint32_t sw256(uint32_t o) { return o ^ ((o >> 4) & 0x70); }

__device__ __forceinline__ void ldsm4(uint32_t r[4], uint32_t addr) {
    asm volatile("ldmatrix.sync.aligned.m8n8.x4.shared.b16 {%0,%1,%2,%3}, [%4];"
        : "=r"(r[0]), "=r"(r[1]), "=r"(r[2]), "=r"(r[3]) : "r"(addr));
}
__device__ __forceinline__ void imma16832(int c[4], const uint32_t a[4], const uint32_t b[2]) {
    asm volatile(
        "mma.sync.aligned.m16n8k32.row.col.s32.s8.s8.s32 "
        "{%0,%1,%2,%3}, {%4,%5,%6,%7}, {%8,%9}, {%0,%1,%2,%3};"
        : "+r"(c[0]), "+r"(c[1]), "+r"(c[2]), "+r"(c[3])
        : "r"(a[0]), "r"(a[1]), "r"(a[2]), "r"(a[3]), "r"(b[0]), "r"(b[1]));
}
// A fragment address: 16x32 s8 tile at (rbase, kbyte kk) of a [rows x 64B] SW64 plane
__device__ __forceinline__ uint32_t xfrag(uint32_t base, int rbase, int kk, int lane) {
    return base + sw64((uint32_t)((rbase + (lane & 15)) * 64 + kk + (lane & 16)));
}
// B fragment address: 32n x 32k s8 at (n0, kbyte kg) of a [64 n x 256B] SW256 plane
__device__ __forceinline__ uint32_t wfrag(uint32_t base, int n0, int kg, int lane) {
    int n  = n0 + (lane & 7) + ((lane >> 4) & 1) * 8;
    int kb = kg + ((lane >> 3) & 1) * 16;
    return base + sw256((uint32_t)(n * 256 + kb));
}
__device__ __forceinline__ void prefetch_l2(const void* p) {
    asm volatile("prefetch.global.L2 [%0];" :: "l"(p));
}
__device__ __forceinline__ uint32_t pack4(int b0, int b1, int b2, int b3) {
    return (uint32_t)(b0 & 0xFF) | ((uint32_t)(b1 & 0xFF) << 8)
         | ((uint32_t)(b2 & 0xFF) << 16) | ((uint32_t)(b3 & 0xFF) << 24);
}
// balanced 2-digit split: v = d1*128 + d0, |d0| <= 64
__device__ __forceinline__ void digits(int v, int& d1, int& d0) {
    d1 = (v + 64) >> 7;
    d0 = ((v + 64) & 127) - 64;
}

__global__ __launch_bounds__(THREADS, 2)
void edge_mlp_imma(const float* __restrict__ src, const float* __restrict__ dst,
                   const float* __restrict__ ea,
                   const float* __restrict__ W1, const float* __restrict__ b1,
                   const float* __restrict__ W2, const float* __restrict__ b2,
                   float* __restrict__ out, int E, int ntiles)
{
    extern __shared__ char smem[];
    const uint32_t sb = smem_u32(smem);
    const int tid = threadIdx.x;
    const int lid = tid & 31;
    const int wid = tid >> 5;

    const int wm = wid & 3;   // M group: rows 32*wm .. +31
    const int wn = wid >> 2;  // N group: cols 32*wn .. +31

    // ================= ONE-TIME: biases + quantized transposed weights =========
    if (tid < 64) {
        ((float*)(smem + OFF_B1))[tid] = b1[tid];
        ((float*)(smem + OFF_B2))[tid] = b2[tid];
    }
    // W1 [192k][64n] fp32 -> planes [64n][256B], scale 2^17
    #pragma unroll 4
    for (int i = 0; i < 48; ++i) {
        int idx = tid + i * THREADS;               // 0..12287
        int k = idx >> 6, n = idx & 63;
        int v = __float2int_rn(W1[idx] * 131072.f);
        int e1, e0; digits(v, e1, e0);
        uint32_t off = sw256((uint32_t)(n * 256 + k));
        *(int8_t*)(smem + OFF_W1E1 + off) = (int8_t)e1;
        *(int8_t*)(smem + OFF_W1E0 + off) = (int8_t)e0;
    }
    // W2 [64k][64n] fp32 -> planes [64n][256B], scale 2^16
    #pragma unroll 4
    for (int i = 0; i < 16; ++i) {
        int idx = tid + i * THREADS;               // 0..4095
        int k = idx >> 6, n = idx & 63;
        int v = __float2int_rn(W2[idx] * 65536.f);
        int e1, e0; digits(v, e1, e0);
        uint32_t off = sw256((uint32_t)(n * 256 + k));
        *(int8_t*)(smem + OFF_W2E1 + off) = (int8_t)e1;
        *(int8_t*)(smem + OFF_W2E0 + off) = (int8_t)e0;
    }

    int accH[2][4][4], accM[2][4][4];
    #pragma unroll
    for (int mt = 0; mt < 2; ++mt)
        #pragma unroll
        for (int nt = 0; nt < 4; ++nt)
            #pragma unroll
            for (int j = 0; j < 4; ++j) { accH[mt][nt][j] = 0; accM[mt][nt][j] = 0; }

    // ---- X staging: batched LDG (MLP=8), quantize scale 2^11, digit planes ----
    auto stage_x = [&](const float* __restrict__ p, int e0, const float* __restrict__ pre) {
        float4 v[8];
        #pragma unroll
        for (int i = 0; i < 8; ++i) {
            int idx = tid + i * THREADS;           // 0..2047
            int e = e0 + (idx >> 4);
            v[i] = (e < E) ? ((const float4*)p)[(size_t)e * 16 + (idx & 15)]
                           : make_float4(0.f, 0.f, 0.f, 0.f);
        }
        if (pre) prefetch_l2((const char*)pre + (size_t)tid * 128);
        #pragma unroll
        for (int i = 0; i < 8; ++i) {
            int idx = tid + i * THREADS;
            uint32_t off = sw64((uint32_t)((idx >> 4) * 64 + (idx & 15) * 4));
            int v0 = __float2int_rn(v[i].x * 2048.f);
            int v1 = __float2int_rn(v[i].y * 2048.f);
            int v2 = __float2int_rn(v[i].z * 2048.f);
            int v3 = __float2int_rn(v[i].w * 2048.f);
            int h0,l0,h1,l1,h2,l2,h3,l3;
            digits(v0,h0,l0); digits(v1,h1,l1); digits(v2,h2,l2); digits(v3,h3,l3);
            *(uint32_t*)(smem + OFF_XD1 + off) = pack4(h0,h1,h2,h3);
            *(uint32_t*)(smem + OFF_XD0 + off) = pack4(l0,l1,l2,l3);
        }
    };

    // one 32-k step: A digits from X planes at kbyte kk, B digits from W planes at kbyte kg
    auto kstep = [&](uint32_t we1, uint32_t we0, int kk, int kg) {
        uint32_t a1[2][4], a0[2][4], be1[2][4], be0[2][4];
        ldsm4(be1[0], wfrag(we1, wn * 32,      kg, lid));
        ldsm4(be1[1], wfrag(we1, wn * 32 + 16, kg, lid));
        ldsm4(be0[0], wfrag(we0, wn * 32,      kg, lid));
        ldsm4(be0[1], wfrag(we0, wn * 32 + 16, kg, lid));
        ldsm4(a1[0], xfrag(sb + OFF_XD1, wm * 32,      kk, lid));
        ldsm4(a1[1], xfrag(sb + OFF_XD1, wm * 32 + 16, kk, lid));
        ldsm4(a0[0], xfrag(sb + OFF_XD0, wm * 32,      kk, lid));
        ldsm4(a0[1], xfrag(sb + OFF_XD0, wm * 32 + 16, kk, lid));
        #pragma unroll
        for (int mt = 0; mt < 2; ++mt)
            #pragma unroll
            for (int nt = 0; nt < 4; ++nt)
                imma16832(accH[mt][nt], a1[mt], &be1[nt >> 1][(nt & 1) * 2]);
        #pragma unroll
        for (int mt = 0; mt < 2; ++mt)
            #pragma unroll
            for (int nt = 0; nt < 4; ++nt)
                imma16832(accM[mt][nt], a1[mt], &be0[nt >> 1][(nt & 1) * 2]);
        #pragma unroll
        for (int mt = 0; mt < 2; ++mt)
            #pragma unroll
            for (int nt = 0; nt < 4; ++nt)
                imma16832(accM[mt][nt], a0[mt], &be1[nt >> 1][(nt & 1) * 2]);
    };

    const uint32_t W1e1 = sb + OFF_W1E1, W1e0 = sb + OFF_W1E0;
    const uint32_t W2e1 = sb + OFF_W2E1, W2e0 = sb + OFF_W2E0;

    // ================= persistent tile loop =================
    for (int t = blockIdx.x; t < ntiles; t += gridDim.x) {
        const int e0 = t * M_TILE;

        stage_x(src, e0, dst + (size_t)e0 * 64);
        __syncthreads();
        kstep(W1e1, W1e0, 0, 0);   kstep(W1e1, W1e0, 32, 32);
        __syncthreads();

        stage_x(dst, e0, ea + (size_t)e0 * 64);
        __syncthreads();
        kstep(W1e1, W1e0, 0, 64);  kstep(W1e1, W1e0, 32, 96);
        __syncthreads();

        {
            int tn = t + gridDim.x;
            const float* nxt = (tn < ntiles) ? src + (size_t)tn * M_TILE * 64
                                             : src + (size_t)e0 * 64;
            stage_x(ea, e0, nxt);
        }
        __syncthreads();
        kstep(W1e1, W1e0, 0, 128); kstep(W1e1, W1e0, 32, 160);
        __syncthreads();                           // GEMM1 reads done; X planes free for H

        // ---- bias1 + ReLU + clamp + quantize (scale 2^12) -> H digit planes ----
        {
            const float* b1s = (const float*)(smem + OFF_B1);
            #pragma unroll
            for (int mt = 0; mt < 2; ++mt)
                #pragma unroll
                for (int nt = 0; nt < 4; ++nt) {
                    int row = wm * 32 + mt * 16 + (lid >> 2);
                    int col = wn * 32 + nt * 8 + (lid & 3) * 2;
                    float bc0 = b1s[col], bc1 = b1s[col + 1];
                    // y1 = accH*2^-14 + accM*2^-21  (x scale 2^-11 * w scale 2^-17)
                    float y0 = (float)accH[mt][nt][0] * 6.103515625e-05f
                             + (float)accM[mt][nt][0] * 4.76837158203125e-07f + bc0;
                    float y1 = (float)accH[mt][nt][1] * 6.103515625e-05f
                             + (float)accM[mt][nt][1] * 4.76837158203125e-07f + bc1;
                    float y2 = (float)accH[mt][nt][2] * 6.103515625e-05f
                             + (float)accM[mt][nt][2] * 4.76837158203125e-07f + bc0;
                    float y3 = (float)accH[mt][nt][3] * 6.103515625e-05f
                             + (float)accM[mt][nt][3] * 4.76837158203125e-07f + bc1;
                    int q0 = __float2int_rn(fminf(fmaxf(y0, 0.f), 3.96f) * 4096.f);
                    int q1 = __float2int_rn(fminf(fmaxf(y1, 0.f), 3.96f) * 4096.f);
                    int q2 = __float2int_rn(fminf(fmaxf(y2, 0.f), 3.96f) * 4096.f);
                    int q3 = __float2int_rn(fminf(fmaxf(y3, 0.f), 3.96f) * 4096.f);
                    int h0,l0,h1,l1,h2,l2,h3,l3;
                    digits(q0,h0,l0); digits(q1,h1,l1);
                    digits(q2,h2,l2); digits(q3,h3,l3);
                    uint32_t oA = sw64((uint32_t)(row * 64 + col));
                    uint32_t oB = sw64((uint32_t)((row + 8) * 64 + col));
                    *(uint16_t*)(smem + OFF_XD1 + oA) = (uint16_t)((h0 & 0xFF) | ((h1 & 0xFF) << 8));
                    *(uint16_t*)(smem + OFF_XD0 + oA) = (uint16_t)((l0 & 0xFF) | ((l1 & 0xFF) << 8));
                    *(uint16_t*)(smem + OFF_XD1 + oB) = (uint16_t)((h2 & 0xFF) | ((h3 & 0xFF) << 8));
                    *(uint16_t*)(smem + OFF_XD0 + oB) = (uint16_t)((l2 & 0xFF) | ((l3 & 0xFF) << 8));
                    #pragma unroll
                    for (int j = 0; j < 4; ++j) { accH[mt][nt][j] = 0; accM[mt][nt][j] = 0; }
                }
        }
        __syncthreads();

        // ================= GEMM2 (K = 64) =================
        kstep(W2e1, W2e0, 0, 0);   kstep(W2e1, W2e0, 32, 32);

        // ---- epilogue: y2 = accH*2^-14 + accM*2^-21 + b2  (H 2^-12 * W2 2^-16) ----
        {
            const float* b2s = (const float*)(smem + OFF_B2);
            #pragma unroll
            for (int mt = 0; mt < 2; ++mt)
                #pragma unroll
                for (int nt = 0; nt < 4; ++nt) {
                    int row = wm * 32 + mt * 16 + (lid >> 2);
                    int col = wn * 32 + nt * 8 + (lid & 3) * 2;
                    float bc0 = b2s[col], bc1 = b2s[col + 1];
                    float y0 = (float)accH[mt][nt][0] * 6.103515625e-05f
                             + (float)accM[mt][nt][0] * 4.76837158203125e-07f + bc0;
                    float y1 = (float)accH[mt][nt][1] * 6.103515625e-05f
                             + (float)accM[mt][nt][1] * 4.76837158203125e-07f + bc1;
                    float y2 = (float)accH[mt][nt][2] * 6.103515625e-05f
                             + (float)accM[mt][nt][2] * 4.76837158203125e-07f + bc0;
                    float y3 = (float)accH[mt][nt][3] * 6.103515625e-05f
                             + (float)accM[mt][nt][3] * 4.76837158203125e-07f + bc1;
                    int eA = e0 + row, eB = e0 + row + 8;
                    if (eA < E) *(float2*)&out[(size_t)eA * 64 + col] = make_float2(y0, y1);
                    if (eB < E) *(float2*)&out[(size_t)eB * 64 + col] = make_float2(y2, y3);
                    #pragma unroll
                    for (int j = 0; j < 4; ++j) { accH[mt][nt][j] = 0; accM[mt][nt][j] = 0; }
                }
        }
        __syncthreads();                           // H reads done before next stage_x
    }
}

extern "C" void kernel_launch(void* const* d_in, const int* in_sizes, int n_in,
                              void* d_out, int out_size)
{
    const float* src = (const float*)d_in[0];
    const float* dst = (const float*)d_in[1];
    const float* ea  = (const float*)d_in[2];
    const float* W1  = (const float*)d_in[5];
    const float* b1  = (const float*)d_in[6];
    const float* W2  = (const float*)d_in[7];
    const float* b2  = (const float*)d_in[8];
    float* out = (float*)d_out;

    int E = in_sizes[0] / 64;
    int ntiles = (E + M_TILE - 1) / M_TILE;

    cudaFuncSetAttribute(edge_mlp_imma,
                         cudaFuncAttributeMaxDynamicSharedMemorySize, SMEM_BYTES);

    int grid = 2 * 148;
    if (grid > ntiles) grid = ntiles;
    edge_mlp_imma<<<grid, THREADS, SMEM_BYTES>>>(src, dst, ea, W1, b1, W2, b2, out, E, ntiles);
}

// round 12
// speedup vs baseline: 2.9643x; 2.9643x over previous
#include <cuda_runtime.h>
#include <cuda_fp16.h>
#include <cstdint>

#define THREADS 256
#define M_TILE  128

// ---------------- SMEM layout (bytes), MMA buffers 1024-aligned ----------------
#define OFF_B1   0
#define OFF_B2   256
#define OFF_XHI  1024
#define OFF_XLO  (OFF_XHI + 16384)     // 17408
#define OFF_W1   (OFF_XLO + 16384)     // 33792  (192 x 64 fp16, 128B rows, SW128)
#define OFF_W2   (OFF_W1 + 24576)      // 58368  (64 x 64 fp16)
#define SMEM_BYTES (OFF_W2 + 8192)     // 66560 -> 3 CTAs/SM

// ---------------- helpers ----------------
__device__ __forceinline__ uint32_t smem_u32(const void* p) {
    uint32_t a;
    asm("{ .reg .u64 t; cvta.to.shared.u64 t, %1; cvt.u32.u64 %0, t; }" : "=r"(a) : "l"(p));
    return a;
}
__device__ __forceinline__ uint32_t sw128(uint32_t o) { return o ^ ((o >> 3) & 0x70); }

__device__ __forceinline__ uint32_t f2h2(float a, float b) {
    __half2 h = __floats2half2_rn(a, b);
    return *(uint32_t*)&h;
}
// split 4 fp32 into fp16 hi (rounded) + fp16 lo (exact residual), 8B store each
__device__ __forceinline__ void split_store(char* hip, char* lop, float4 v) {
    uint32_t h01 = f2h2(v.x, v.y);
    uint32_t h23 = f2h2(v.z, v.w);
    float2 f01 = __half22float2(*(__half2*)&h01);
    float2 f23 = __half22float2(*(__half2*)&h23);
    uint32_t l01 = f2h2(v.x - f01.x, v.y - f01.y);
    uint32_t l23 = f2h2(v.z - f23.x, v.w - f23.y);
    *reinterpret_cast<uint2*>(hip) = make_uint2(h01, h23);
    *reinterpret_cast<uint2*>(lop) = make_uint2(l01, l23);
}

__device__ __forceinline__ void ldsm4(uint32_t r[4], uint32_t addr) {
    asm volatile("ldmatrix.sync.aligned.m8n8.x4.shared.b16 {%0,%1,%2,%3}, [%4];"
        : "=r"(r[0]), "=r"(r[1]), "=r"(r[2]), "=r"(r[3]) : "r"(addr));
}
__device__ __forceinline__ void ldsm4t(uint32_t r[4], uint32_t addr) {
    asm volatile("ldmatrix.sync.aligned.m8n8.x4.trans.shared.b16 {%0,%1,%2,%3}, [%4];"
        : "=r"(r[0]), "=r"(r[1]), "=r"(r[2]), "=r"(r[3]) : "r"(addr));
}
__device__ __forceinline__ void mma16816(float c[4], const uint32_t a[4], const uint32_t b[2]) {
    asm volatile(
        "mma.sync.aligned.m16n8k16.row.col.f32.f16.f16.f32 "
        "{%0,%1,%2,%3}, {%4,%5,%6,%7}, {%8,%9}, {%0,%1,%2,%3};"
        : "+f"(c[0]), "+f"(c[1]), "+f"(c[2]), "+f"(c[3])
        : "r"(a[0]), "r"(a[1]), "r"(a[2]), "r"(a[3]), "r"(b[0]), "r"(b[1]));
}
__device__ __forceinline__ uint32_t frag_addr(uint32_t base, int rbase, int cbase, int lane) {
    int row  = rbase + (lane & 15);
    int colb = cbase * 2 + (lane & 16);
    return base + sw128((uint32_t)(row * 128 + colb));
}
__device__ __forceinline__ void prefetch_l2(const void* p) {
    asm volatile("prefetch.global.L2 [%0];" :: "l"(p));
}

__global__ __launch_bounds__(THREADS, 3)
void edge_mlp_f16(const float* __restrict__ src, const float* __restrict__ dst,
                  const float* __restrict__ ea,
                  const float* __restrict__ W1, const float* __restrict__ b1,
                  const float* __restrict__ W2, const float* __restrict__ b2,
                  float* __restrict__ out, int E, int ntiles)
{
    extern __shared__ char smem[];
    const uint32_t sb = smem_u32(smem);
    const int tid = threadIdx.x;
    const int lid = tid & 31;
    const int wid = tid >> 5;

    const int wm = wid & 3;   // M group: rows 32*wm .. +31
    const int wn = wid >> 2;  // N group: cols 32*wn .. +31

    // ================= ONE-TIME: biases + fp16 weights (single plane) ==========
    if (tid < 64) {
        ((float*)(smem + OFF_B1))[tid] = b1[tid];
        ((float*)(smem + OFF_B2))[tid] = b2[tid];
    }
    #pragma unroll
    for (int i = 0; i < 12; ++i) {
        int idx = tid + i * THREADS;               // float4 index, 0..3071
        float4 v = ((const float4*)W1)[idx];
        uint32_t off = sw128((uint32_t)((idx >> 4) * 128 + (idx & 15) * 8));
        *(uint2*)(smem + OFF_W1 + off) = make_uint2(f2h2(v.x, v.y), f2h2(v.z, v.w));
    }
    #pragma unroll
    for (int i = 0; i < 4; ++i) {
        int idx = tid + i * THREADS;               // 0..1023
        float4 v = ((const float4*)W2)[idx];
        uint32_t off = sw128((uint32_t)((idx >> 4) * 128 + (idx & 15) * 8));
        *(uint2*)(smem + OFF_W2 + off) = make_uint2(f2h2(v.x, v.y), f2h2(v.z, v.w));
    }

    float acc[2][4][4];
    #pragma unroll
    for (int mt = 0; mt < 2; ++mt)
        #pragma unroll
        for (int nt = 0; nt < 4; ++nt)
            #pragma unroll
            for (int j = 0; j < 4; ++j) acc[mt][nt][j] = 0.f;

    // ---- X staging: two batches of 4 LDGs (keeps reg pressure under 85) ----
    auto stage_x = [&](const float* __restrict__ p, int e0, const float* __restrict__ pre) {
        #pragma unroll
        for (int g = 0; g < 2; ++g) {
            float4 v[4];
            #pragma unroll
            for (int i = 0; i < 4; ++i) {
                int idx = tid + (g * 4 + i) * THREADS;   // 0..2047
                int e = e0 + (idx >> 4);
                v[i] = (e < E) ? ((const float4*)p)[(size_t)e * 16 + (idx & 15)]
                               : make_float4(0.f, 0.f, 0.f, 0.f);
            }
            if (g == 0 && pre) prefetch_l2((const char*)pre + (size_t)tid * 128);
            #pragma unroll
            for (int i = 0; i < 4; ++i) {
                int idx = tid + (g * 4 + i) * THREADS;
                uint32_t off = sw128((uint32_t)((idx >> 4) * 128 + (idx & 15) * 8));
                split_store(smem + OFF_XHI + off, smem + OFF_XLO + off, v[i]);
            }
        }
    };

    // one 16-wide k-step, 2 terms: acc += xh*w ; acc += xl*w
    auto kstep = [&](int kk, uint32_t wb, int kg) {
        uint32_t bf[2][4], ahi[2][4], alo[2][4];
        ldsm4t(bf[0], frag_addr(wb, kg, wn * 32,      lid));
        ldsm4t(bf[1], frag_addr(wb, kg, wn * 32 + 16, lid));
        ldsm4(ahi[0], frag_addr(sb + OFF_XHI, wm * 32,      kk, lid));
        ldsm4(ahi[1], frag_addr(sb + OFF_XHI, wm * 32 + 16, kk, lid));
        ldsm4(alo[0], frag_addr(sb + OFF_XLO, wm * 32,      kk, lid));
        ldsm4(alo[1], frag_addr(sb + OFF_XLO, wm * 32 + 16, kk, lid));
        #pragma unroll
        for (int mt = 0; mt < 2; ++mt)
            #pragma unroll
            for (int nt = 0; nt < 4; ++nt)
                mma16816(acc[mt][nt], ahi[mt], &bf[nt >> 1][(nt & 1) * 2]);
        #pragma unroll
        for (int mt = 0; mt < 2; ++mt)
            #pragma unroll
            for (int nt = 0; nt < 4; ++nt)
                mma16816(acc[mt][nt], alo[mt], &bf[nt >> 1][(nt & 1) * 2]);
    };

    // ================= persistent tile loop =================
    for (int t = blockIdx.x; t < ntiles; t += gridDim.x) {
        const int e0 = t * M_TILE;

        stage_x(src, e0, dst + (size_t)e0 * 64);
        __syncthreads();
        #pragma unroll
        for (int ks = 0; ks < 4; ++ks) kstep(ks * 16, sb + OFF_W1, ks * 16);
        __syncthreads();

        stage_x(dst, e0, ea + (size_t)e0 * 64);
        __syncthreads();
        #pragma unroll
        for (int ks = 0; ks < 4; ++ks) kstep(ks * 16, sb + OFF_W1, 64 + ks * 16);
        __syncthreads();

        {
            int tn = t + gridDim.x;
            const float* nxt = (tn < ntiles) ? src + (size_t)tn * M_TILE * 64
                                             : src + (size_t)e0 * 64;
            stage_x(ea, e0, nxt);
        }
        __syncthreads();
        #pragma unroll
        for (int ks = 0; ks < 4; ++ks) kstep(ks * 16, sb + OFF_W1, 128 + ks * 16);
        __syncthreads();                           // GEMM1 reads done; X free for H

        // ---- bias1 + ReLU + fp16 2-digit split -> H (reuse X hi/lo) ----
        {
            const float* b1s = (const float*)(smem + OFF_B1);
            #pragma unroll
            for (int mt = 0; mt < 2; ++mt)
                #pragma unroll
                for (int nt = 0; nt < 4; ++nt) {
                    int row = wm * 32 + mt * 16 + (lid >> 2);
                    int col = wn * 32 + nt * 8 + (lid & 3) * 2;
                    float bc0 = b1s[col], bc1 = b1s[col + 1];
                    float h0 = fmaxf(acc[mt][nt][0] + bc0, 0.f);
                    float h1 = fmaxf(acc[mt][nt][1] + bc1, 0.f);
                    float h2 = fmaxf(acc[mt][nt][2] + bc0, 0.f);
                    float h3 = fmaxf(acc[mt][nt][3] + bc1, 0.f);
                    uint32_t hA = f2h2(h0, h1);
                    uint32_t hB = f2h2(h2, h3);
                    float2 fA = __half22float2(*(__half2*)&hA);
                    float2 fB = __half22float2(*(__half2*)&hB);
                    uint32_t lA = f2h2(h0 - fA.x, h1 - fA.y);
                    uint32_t lB = f2h2(h2 - fB.x, h3 - fB.y);
                    uint32_t oA = sw128((uint32_t)(row * 128 + col * 2));
                    uint32_t oB = sw128((uint32_t)((row + 8) * 128 + col * 2));
                    *(uint32_t*)(smem + OFF_XHI + oA) = hA;
                    *(uint32_t*)(smem + OFF_XLO + oA) = lA;
                    *(uint32_t*)(smem + OFF_XHI + oB) = hB;
                    *(uint32_t*)(smem + OFF_XLO + oB) = lB;
                    acc[mt][nt][0] = acc[mt][nt][1] = acc[mt][nt][2] = acc[mt][nt][3] = 0.f;
                }
        }
        __syncthreads();

        // ================= GEMM2 (K = 64) =================
        #pragma unroll
        for (int ks = 0; ks < 4; ++ks) kstep(ks * 16, sb + OFF_W2, ks * 16);

        // ---- epilogue: + bias2, float2 stores; reset acc for next tile ----
        {
            const float* b2s = (const float*)(smem + OFF_B2);
            #pragma unroll
            for (int mt = 0; mt < 2; ++mt)
                #pragma unroll
                for (int nt = 0; nt < 4; ++nt) {
                    int row = wm * 32 + mt * 16 + (lid >> 2);
                    int col = wn * 32 + nt * 8 + (lid & 3) * 2;
                    float bc0 = b2s[col], bc1 = b2s[col + 1];
                    int eA = e0 + row, eB = e0 + row + 8;
                    if (eA < E)
                        *(float2*)&out[(size_t)eA * 64 + col] =
                            make_float2(acc[mt][nt][0] + bc0, acc[mt][nt][1] + bc1);
                    if (eB < E)
                        *(float2*)&out[(size_t)eB * 64 + col] =
                            make_float2(acc[mt][nt][2] + bc0, acc[mt][nt][3] + bc1);
                    acc[mt][nt][0] = acc[mt][nt][1] = acc[mt][nt][2] = acc[mt][nt][3] = 0.f;
                }
        }
        __syncthreads();                           // H reads done before next stage_x
    }
}

extern "C" void kernel_launch(void* const* d_in, const int* in_sizes, int n_in,
                              void* d_out, int out_size)
{
    const float* src = (const float*)d_in[0];
    const float* dst = (const float*)d_in[1];
    const float* ea  = (const float*)d_in[2];
    const float* W1  = (const float*)d_in[5];
    const float* b1  = (const float*)d_in[6];
    const float* W2  = (const float*)d_in[7];
    const float* b2  = (const float*)d_in[8];
    float* out = (float*)d_out;

    int E = in_sizes[0] / 64;
    int ntiles = (E + M_TILE - 1) / M_TILE;

    cudaFuncSetAttribute(edge_mlp_f16,
                         cudaFuncAttributeMaxDynamicSharedMemorySize, SMEM_BYTES);

    int grid = 3 * 148;
    if (grid > ntiles) grid = ntiles;
    edge_mlp_f16<<<grid, THREADS, SMEM_BYTES>>>(src, dst, ea, W1, b1, W2, b2, out, E, ntiles);
}

// round 13
// speedup vs baseline: 3.7930x; 1.2796x over previous
#include <cuda_runtime.h>
#include <cuda_fp16.h>
#include <cstdint>

#define THREADS 256
#define M_TILE  128

// ---------------- SMEM layout (bytes), MMA buffers 1024-aligned ----------------
#define OFF_B1   0
#define OFF_B2   256
#define OFF_X    1024                  // 128 x 64 fp16 (128B rows, SW128) = 16384
#define OFF_W1   (OFF_X + 16384)       // 17408  (192 x 64 fp16) = 24576
#define OFF_W2   (OFF_W1 + 24576)      // 41984  (64 x 64 fp16)  = 8192
#define SMEM_BYTES (OFF_W2 + 8192)     // 50176 -> 3 CTAs/SM (RF-capped)

// ---------------- helpers ----------------
__device__ __forceinline__ uint32_t smem_u32(const void* p) {
    uint32_t a;
    asm("{ .reg .u64 t; cvta.to.shared.u64 t, %1; cvt.u32.u64 %0, t; }" : "=r"(a) : "l"(p));
    return a;
}
__device__ __forceinline__ uint32_t sw128(uint32_t o) { return o ^ ((o >> 3) & 0x70); }

__device__ __forceinline__ uint32_t f2h2(float a, float b) {
    __half2 h = __floats2half2_rn(a, b);
    return *(uint32_t*)&h;
}

__device__ __forceinline__ void ldsm4(uint32_t r[4], uint32_t addr) {
    asm volatile("ldmatrix.sync.aligned.m8n8.x4.shared.b16 {%0,%1,%2,%3}, [%4];"
        : "=r"(r[0]), "=r"(r[1]), "=r"(r[2]), "=r"(r[3]) : "r"(addr));
}
__device__ __forceinline__ void ldsm4t(uint32_t r[4], uint32_t addr) {
    asm volatile("ldmatrix.sync.aligned.m8n8.x4.trans.shared.b16 {%0,%1,%2,%3}, [%4];"
        : "=r"(r[0]), "=r"(r[1]), "=r"(r[2]), "=r"(r[3]) : "r"(addr));
}
__device__ __forceinline__ void mma16816(float c[4], const uint32_t a[4], const uint32_t b[2]) {
    asm volatile(
        "mma.sync.aligned.m16n8k16.row.col.f32.f16.f16.f32 "
        "{%0,%1,%2,%3}, {%4,%5,%6,%7}, {%8,%9}, {%0,%1,%2,%3};"
        : "+f"(c[0]), "+f"(c[1]), "+f"(c[2]), "+f"(c[3])
        : "r"(a[0]), "r"(a[1]), "r"(a[2]), "r"(a[3]), "r"(b[0]), "r"(b[1]));
}
__device__ __forceinline__ uint32_t frag_addr(uint32_t base, int rbase, int cbase, int lane) {
    int row  = rbase + (lane & 15);
    int colb = cbase * 2 + (lane & 16);
    return base + sw128((uint32_t)(row * 128 + colb));
}
__device__ __forceinline__ void prefetch_l2(const void* p) {
    asm volatile("prefetch.global.L2 [%0];" :: "l"(p));
}

__global__ __launch_bounds__(THREADS, 3)
void edge_mlp_f16(const float* __restrict__ src, const float* __restrict__ dst,
                  const float* __restrict__ ea,
                  const float* __restrict__ W1, const float* __restrict__ b1,
                  const float* __restrict__ W2, const float* __restrict__ b2,
                  float* __restrict__ out, int E, int ntiles)
{
    extern __shared__ char smem[];
    const uint32_t sb = smem_u32(smem);
    const int tid = threadIdx.x;
    const int lid = tid & 31;
    const int wid = tid >> 5;

    const int wm = wid & 3;   // M group: rows 32*wm .. +31
    const int wn = wid >> 2;  // N group: cols 32*wn .. +31

    // ================= ONE-TIME: biases + fp16 weights =================
    if (tid < 64) {
        ((float*)(smem + OFF_B1))[tid] = b1[tid];
        ((float*)(smem + OFF_B2))[tid] = b2[tid];
    }
    #pragma unroll
    for (int i = 0; i < 12; ++i) {
        int idx = tid + i * THREADS;               // float4 index, 0..3071
        float4 v = ((const float4*)W1)[idx];
        uint32_t off = sw128((uint32_t)((idx >> 4) * 128 + (idx & 15) * 8));
        *(uint2*)(smem + OFF_W1 + off) = make_uint2(f2h2(v.x, v.y), f2h2(v.z, v.w));
    }
    #pragma unroll
    for (int i = 0; i < 4; ++i) {
        int idx = tid + i * THREADS;               // 0..1023
        float4 v = ((const float4*)W2)[idx];
        uint32_t off = sw128((uint32_t)((idx >> 4) * 128 + (idx & 15) * 8));
        *(uint2*)(smem + OFF_W2 + off) = make_uint2(f2h2(v.x, v.y), f2h2(v.z, v.w));
    }

    float acc[2][4][4];
    #pragma unroll
    for (int mt = 0; mt < 2; ++mt)
        #pragma unroll
        for (int nt = 0; nt < 4; ++nt)
            #pragma unroll
            for (int j = 0; j < 4; ++j) acc[mt][nt][j] = 0.f;

    // ---- X staging: two batches of 4 LDGs, single fp16 plane ----
    auto stage_x = [&](const float* __restrict__ p, int e0, const float* __restrict__ pre) {
        #pragma unroll
        for (int g = 0; g < 2; ++g) {
            float4 v[4];
            #pragma unroll
            for (int i = 0; i < 4; ++i) {
                int idx = tid + (g * 4 + i) * THREADS;   // 0..2047
                int e = e0 + (idx >> 4);
                v[i] = (e < E) ? ((const float4*)p)[(size_t)e * 16 + (idx & 15)]
                               : make_float4(0.f, 0.f, 0.f, 0.f);
            }
            if (g == 0 && pre) prefetch_l2((const char*)pre + (size_t)tid * 128);
            #pragma unroll
            for (int i = 0; i < 4; ++i) {
                int idx = tid + (g * 4 + i) * THREADS;
                uint32_t off = sw128((uint32_t)((idx >> 4) * 128 + (idx & 15) * 8));
                *(uint2*)(smem + OFF_X + off) =
                    make_uint2(f2h2(v[i].x, v[i].y), f2h2(v[i].z, v[i].w));
            }
        }
    };

    // one 16-wide k-step, 1 term: acc += x*w
    auto kstep = [&](int kk, uint32_t wb, int kg) {
        uint32_t bf[2][4], af[2][4];
        ldsm4t(bf[0], frag_addr(wb, kg, wn * 32,      lid));
        ldsm4t(bf[1], frag_addr(wb, kg, wn * 32 + 16, lid));
        ldsm4(af[0], frag_addr(sb + OFF_X, wm * 32,      kk, lid));
        ldsm4(af[1], frag_addr(sb + OFF_X, wm * 32 + 16, kk, lid));
        #pragma unroll
        for (int mt = 0; mt < 2; ++mt)
            #pragma unroll
            for (int nt = 0; nt < 4; ++nt)
                mma16816(acc[mt][nt], af[mt], &bf[nt >> 1][(nt & 1) * 2]);
    };

    // ================= persistent tile loop =================
    for (int t = blockIdx.x; t < ntiles; t += gridDim.x) {
        const int e0 = t * M_TILE;

        stage_x(src, e0, dst + (size_t)e0 * 64);
        __syncthreads();
        #pragma unroll
        for (int ks = 0; ks < 4; ++ks) kstep(ks * 16, sb + OFF_W1, ks * 16);
        __syncthreads();

        stage_x(dst, e0, ea + (size_t)e0 * 64);
        __syncthreads();
        #pragma unroll
        for (int ks = 0; ks < 4; ++ks) kstep(ks * 16, sb + OFF_W1, 64 + ks * 16);
        __syncthreads();

        {
            int tn = t + gridDim.x;
            const float* nxt = (tn < ntiles) ? src + (size_t)tn * M_TILE * 64
                                             : src + (size_t)e0 * 64;
            stage_x(ea, e0, nxt);
        }
        __syncthreads();
        #pragma unroll
        for (int ks = 0; ks < 4; ++ks) kstep(ks * 16, sb + OFF_W1, 128 + ks * 16);
        __syncthreads();                           // GEMM1 reads done; X free for H

        // ---- bias1 + ReLU -> single fp16 H plane (reuse X) ----
        {
            const float* b1s = (const float*)(smem + OFF_B1);
            #pragma unroll
            for (int mt = 0; mt < 2; ++mt)
                #pragma unroll
                for (int nt = 0; nt < 4; ++nt) {
                    int row = wm * 32 + mt * 16 + (lid >> 2);
                    int col = wn * 32 + nt * 8 + (lid & 3) * 2;
                    float bc0 = b1s[col], bc1 = b1s[col + 1];
                    float h0 = fmaxf(acc[mt][nt][0] + bc0, 0.f);
                    float h1 = fmaxf(acc[mt][nt][1] + bc1, 0.f);
                    float h2 = fmaxf(acc[mt][nt][2] + bc0, 0.f);
                    float h3 = fmaxf(acc[mt][nt][3] + bc1, 0.f);
                    uint32_t oA = sw128((uint32_t)(row * 128 + col * 2));
                    uint32_t oB = sw128((uint32_t)((row + 8) * 128 + col * 2));
                    *(uint32_t*)(smem + OFF_X + oA) = f2h2(h0, h1);
                    *(uint32_t*)(smem + OFF_X + oB) = f2h2(h2, h3);
                    acc[mt][nt][0] = acc[mt][nt][1] = acc[mt][nt][2] = acc[mt][nt][3] = 0.f;
                }
        }
        __syncthreads();

        // ================= GEMM2 (K = 64) =================
        #pragma unroll
        for (int ks = 0; ks < 4; ++ks) kstep(ks * 16, sb + OFF_W2, ks * 16);

        // ---- epilogue: + bias2, float2 stores; reset acc for next tile ----
        {
            const float* b2s = (const float*)(smem + OFF_B2);
            #pragma unroll
            for (int mt = 0; mt < 2; ++mt)
                #pragma unroll
                for (int nt = 0; nt < 4; ++nt) {
                    int row = wm * 32 + mt * 16 + (lid >> 2);
                    int col = wn * 32 + nt * 8 + (lid & 3) * 2;
                    float bc0 = b2s[col], bc1 = b2s[col + 1];
                    int eA = e0 + row, eB = e0 + row + 8;
                    if (eA < E)
                        *(float2*)&out[(size_t)eA * 64 + col] =
                            make_float2(acc[mt][nt][0] + bc0, acc[mt][nt][1] + bc1);
                    if (eB < E)
                        *(float2*)&out[(size_t)eB * 64 + col] =
                            make_float2(acc[mt][nt][2] + bc0, acc[mt][nt][3] + bc1);
                    acc[mt][nt][0] = acc[mt][nt][1] = acc[mt][nt][2] = acc[mt][nt][3] = 0.f;
                }
        }
        __syncthreads();                           // H reads done before next stage_x
    }
}

extern "C" void kernel_launch(void* const* d_in, const int* in_sizes, int n_in,
                              void* d_out, int out_size)
{
    const float* src = (const float*)d_in[0];
    const float* dst = (const float*)d_in[1];
    const float* ea  = (const float*)d_in[2];
    const float* W1  = (const float*)d_in[5];
    const float* b1  = (const float*)d_in[6];
    const float* W2  = (const float*)d_in[7];
    const float* b2  = (const float*)d_in[8];
    float* out = (float*)d_out;

    int E = in_sizes[0] / 64;
    int ntiles = (E + M_TILE - 1) / M_TILE;

    cudaFuncSetAttribute(edge_mlp_f16,
                         cudaFuncAttributeMaxDynamicSharedMemorySize, SMEM_BYTES);

    int grid = 3 * 148;
    if (grid > ntiles) grid = ntiles;
    edge_mlp_f16<<<grid, THREADS, SMEM_BYTES>>>(src, dst, ea, W1, b1, W2, b2, out, E, ntiles);
}